// round 15
// baseline (speedup 1.0000x reference)
#include <cuda_runtime.h>
#include <cuda_fp16.h>
#include <mma.h>

using namespace nvcuda;

// Problem constants (fixed shapes for this problem instance)
#define N_CELL   66
#define N_NODES  30000
#define FDIM     256
#define FD2      128               // half2 per row
#define E_TOT    960000            // directed edges (both directions)
#define NF       (N_NODES * FDIM)  // 7,680,000
#define NF4      (NF / 4)
#define CELL4    ((N_CELL * FDIM) / 4)
#define BN_EPS   1e-5f
#define FPSCALE  16777216.0f       // 2^24 fixed-point for packed degree
#define NBLK     118               // ceil(30000/256) scan blocks

// GEMM tiling
#define GBM 128
#define GBN 64
#define GBK 64
#define GMB 235                    // ceil(30000/128)
#define LDA 72                     // smem half stride (64 k + 8 pad)
#define LDC 72                     // smem float stride (64 n + 8 pad)

// ---------------- device scratch (static, no allocation) ----------------
// g_packed is zero at module load; k_scan_a re-zeros it after reading each
// call, so every kernel_launch (incl. graph replays) sees it zeroed.
__device__ __half2 g_hx0[N_NODES * FD2];   // fp16 feature ping
__device__ __half2 g_hx1[N_NODES * FD2];   // fp16 feature pong
__device__ float  g_x0[NF];                // fp32 GEMM2 output
__device__ __half g_hw1[FDIM * FDIM];      // fp16 W1
__device__ __half g_hw2[FDIM * FDIM];      // fp16 W2
__device__ unsigned long long g_packed[N_NODES];  // (count<<48)|fixed24.24 deg-1
__device__ float g_dinv[N_NODES];
__device__ int   g_colptr[N_NODES + 1];
__device__ int   g_cursor[N_NODES];
__device__ int   g_bsum[NBLK];
__device__ int2  g_epack[E_TOT];           // (src row, norm as bits)
__device__ float g_gp1[4 * GMB * GBN];     // per-block BN partial sums
__device__ float g_gp2[4 * GMB * GBN];     // per-block BN partial sumsq
__device__ float g_scale[FDIM];
__device__ float g_shift[FDIM];

// ------- setup: concat + fp16 quantize + W cvt + degree histogram ---------
// g_packed requires no init (zeroed at load / re-zeroed by k_scan_a).
__global__ void k_concat_setup(const float4* __restrict__ cell,
                               const float4* __restrict__ sub,
                               const float* __restrict__ W1,
                               const float* __restrict__ W2,
                               const int* __restrict__ ei,
                               const float* __restrict__ ew) {
    int i = blockIdx.x * blockDim.x + threadIdx.x;
    if (i < NF4) {
        float4 v = (i < CELL4) ? cell[i] : sub[i - CELL4];
        g_hx0[i * 2]     = __floats2half2_rn(v.x, v.y);
        g_hx0[i * 2 + 1] = __floats2half2_rn(v.z, v.w);
    }
    if (i < FDIM * FDIM) {
        g_hw1[i] = __float2half_rn(W1[i]);
        g_hw2[i] = __float2half_rn(W2[i]);
    }
    if (i < E_TOT) {
        int c = ei[E_TOT + i];             // target (col)
        unsigned long long add = (1ULL << 48) |
            (unsigned long long)__float2uint_rn(ew[i] * FPSCALE);
        atomicAdd(&g_packed[c], add);
    }
}

// ---- scan stage A: decode (+reset packed) + per-block exclusive scan ------
__global__ __launch_bounds__(256) void k_scan_a() {
    __shared__ int sm[256];
    int t = threadIdx.x;
    int i = blockIdx.x * 256 + t;
    int c = 0;
    if (i < N_NODES) {
        unsigned long long p = g_packed[i];
        g_packed[i] = 0ULL;                // leave zeroed for next call
        c = (int)(p >> 48);
        // self-loop weight 1.0 added here
        float deg = (float)(p & 0xFFFFFFFFFFFFULL) * (1.0f / FPSCALE) + 1.0f;
        g_dinv[i] = rsqrtf(deg);           // deg >= 1 always
    }
    sm[t] = c;
    __syncthreads();
#pragma unroll
    for (int off = 1; off < 256; off <<= 1) {
        int v = (t >= off) ? sm[t - off] : 0;
        __syncthreads();
        sm[t] += v;
        __syncthreads();
    }
    if (i < N_NODES) g_colptr[i] = sm[t] - c;        // local exclusive prefix
    if (t == 255) g_bsum[blockIdx.x] = sm[255];      // block total
}

// ---- scan stage C: every block rescans the 118 block totals (redundant) ---
__global__ __launch_bounds__(256) void k_scan_c() {
    __shared__ int sm[128];
    int t = threadIdx.x;
    if (t < 128) {
        int v = (t < NBLK) ? g_bsum[t] : 0;
        sm[t] = v;
    }
    __syncthreads();
#pragma unroll
    for (int off = 1; off < 128; off <<= 1) {
        int u = 0;
        if (t < 128 && t >= off) u = sm[t - off];
        __syncthreads();
        if (t < 128) sm[t] += u;
        __syncthreads();
    }
    int boff = (blockIdx.x == 0) ? 0 : sm[blockIdx.x - 1];
    int i = blockIdx.x * 256 + t;
    if (i < N_NODES) {
        int v = g_colptr[i] + boff;
        g_colptr[i] = v;
        g_cursor[i] = v;
    }
    if (blockIdx.x == 0 && t == 0) g_colptr[N_NODES] = E_TOT;
}

// 8 edges per thread: deep MLP over the 318-cyc ATOMG latency
__global__ __launch_bounds__(256) void k_scatter(const int* __restrict__ ei,
                                                 const float* __restrict__ ew) {
    int e = (blockIdx.x * blockDim.x + threadIdx.x) * 8;
    if (e >= E_TOT) return;
    int4   ra = *reinterpret_cast<const int4*>(&ei[e]);
    int4   rb = *reinterpret_cast<const int4*>(&ei[e + 4]);
    int4   ca = *reinterpret_cast<const int4*>(&ei[E_TOT + e]);
    int4   cb = *reinterpret_cast<const int4*>(&ei[E_TOT + e + 4]);
    float4 wa = *reinterpret_cast<const float4*>(&ew[e]);
    float4 wb = *reinterpret_cast<const float4*>(&ew[e + 4]);

    int   r[8] = {ra.x, ra.y, ra.z, ra.w, rb.x, rb.y, rb.z, rb.w};
    int   c[8] = {ca.x, ca.y, ca.z, ca.w, cb.x, cb.y, cb.z, cb.w};
    float w[8] = {wa.x, wa.y, wa.z, wa.w, wb.x, wb.y, wb.z, wb.w};

    float n[8];
#pragma unroll
    for (int k = 0; k < 8; k++) n[k] = g_dinv[r[k]] * w[k] * g_dinv[c[k]];
    int p[8];
#pragma unroll
    for (int k = 0; k < 8; k++) p[k] = atomicAdd(&g_cursor[c[k]], 1);
#pragma unroll
    for (int k = 0; k < 8; k++)
        g_epack[p[k]] = make_int2(r[k], __float_as_int(n[k]));
}

// ---------------- SpMM: one WARP per destination node, zero sync ----------
// Lane owns 8 features (16B, LDG.128). Warp walks its node's full edge list.
// SRC0: src = hx0, dst = hx1 (else swapped)
// FOLD: out = scale[f]*acc + shift[f]*sum_w   (BN applied via linearity)
template <bool SRC0, bool FOLD>
__global__ __launch_bounds__(256) void k_spmm() {
    const __half2* __restrict__ xin  = SRC0 ? g_hx0 : g_hx1;
    __half2*       __restrict__ xout = SRC0 ? g_hx1 : g_hx0;

    int node = blockIdx.x * 8 + (threadIdx.x >> 5);   // grid 3750 * 8 = 30000
    int lid  = threadIdx.x & 31;
    int beg = g_colptr[node];
    int end = g_colptr[node + 1];
    float di = g_dinv[node];
    float selfw = di * di;

    // self-loop term
    uint4 s = *reinterpret_cast<const uint4*>(&xin[node * FD2 + lid * 4]);
    float2 s0 = __half22float2(*reinterpret_cast<__half2*>(&s.x));
    float2 s1 = __half22float2(*reinterpret_cast<__half2*>(&s.y));
    float2 s2 = __half22float2(*reinterpret_cast<__half2*>(&s.z));
    float2 s3 = __half22float2(*reinterpret_cast<__half2*>(&s.w));
    float acc[8];
    acc[0] = selfw * s0.x; acc[1] = selfw * s0.y;
    acc[2] = selfw * s1.x; acc[3] = selfw * s1.y;
    acc[4] = selfw * s2.x; acc[5] = selfw * s2.y;
    acc[6] = selfw * s3.x; acc[7] = selfw * s3.y;
    float sw = selfw;   // only used when FOLD

#pragma unroll 8
    for (int e = beg; e < end; e++) {
        int2 p = g_epack[e];                 // warp-uniform, L1-resident
        float w = __int_as_float(p.y);
        uint4 d = *reinterpret_cast<const uint4*>(&xin[p.x * FD2 + lid * 4]);
        float2 f0 = __half22float2(*reinterpret_cast<__half2*>(&d.x));
        float2 f1 = __half22float2(*reinterpret_cast<__half2*>(&d.y));
        float2 f2 = __half22float2(*reinterpret_cast<__half2*>(&d.z));
        float2 f3 = __half22float2(*reinterpret_cast<__half2*>(&d.w));
        acc[0] += w * f0.x; acc[1] += w * f0.y;
        acc[2] += w * f1.x; acc[3] += w * f1.y;
        acc[4] += w * f2.x; acc[5] += w * f2.y;
        acc[6] += w * f3.x; acc[7] += w * f3.y;
        if (FOLD) sw += w;                   // lane-uniform, no reduction needed
    }

    if (FOLD) {
        int f0 = lid * 8;
        float4 sca = *reinterpret_cast<const float4*>(&g_scale[f0]);
        float4 scb = *reinterpret_cast<const float4*>(&g_scale[f0 + 4]);
        float4 sha = *reinterpret_cast<const float4*>(&g_shift[f0]);
        float4 shb = *reinterpret_cast<const float4*>(&g_shift[f0 + 4]);
        acc[0] = sca.x * acc[0] + sha.x * sw;
        acc[1] = sca.y * acc[1] + sha.y * sw;
        acc[2] = sca.z * acc[2] + sha.z * sw;
        acc[3] = sca.w * acc[3] + sha.w * sw;
        acc[4] = scb.x * acc[4] + shb.x * sw;
        acc[5] = scb.y * acc[5] + shb.y * sw;
        acc[6] = scb.z * acc[6] + shb.z * sw;
        acc[7] = scb.w * acc[7] + shb.w * sw;
    }

    uint4 o;
    *reinterpret_cast<__half2*>(&o.x) = __floats2half2_rn(acc[0], acc[1]);
    *reinterpret_cast<__half2*>(&o.y) = __floats2half2_rn(acc[2], acc[3]);
    *reinterpret_cast<__half2*>(&o.z) = __floats2half2_rn(acc[4], acc[5]);
    *reinterpret_cast<__half2*>(&o.w) = __floats2half2_rn(acc[6], acc[7]);
    *reinterpret_cast<uint4*>(&xout[node * FD2 + lid * 4]) = o;
}

// ------- fused tensor-core GEMM: C = prelu(A @ W^T + b), + BN stats --------
// A = g_hx1 [N,256] fp16 row-major.  W fp16 [256,256] row-major (= B col-major).
// USE_W1 selects the __device__ weight array; OUT_HALF -> g_hx0 else g_x0.
template <bool USE_W1, bool OUT_HALF>
__global__ __launch_bounds__(256) void k_gemm_tc(const float* __restrict__ bias,
                                                 const float* __restrict__ pw) {
    // smem: mainloop A/B tiles overlap epilogue C staging; dual reduction bufs
    __shared__ __align__(16) unsigned char raw[GBM * LDC * 4 + 32 * GBN * 4];
    __half* As = reinterpret_cast<__half*>(raw);                 // [128][LDA]
    __half* Bs = reinterpret_cast<__half*>(raw + GBM * LDA * 2); // [64][LDA]
    float*  Cs = reinterpret_cast<float*>(raw);                  // [128][LDC]
    float(*Red1)[GBN] = reinterpret_cast<float(*)[GBN]>(raw + GBM * LDC * 4);
    float(*Red2)[GBN] = reinterpret_cast<float(*)[GBN]>(raw + GBM * LDC * 4 + 16 * GBN * 4);

    const __half* __restrict__ A  = reinterpret_cast<const __half*>(g_hx1);
    const __half* __restrict__ hW = USE_W1 ? g_hw1 : g_hw2;

    int bm = blockIdx.x * GBM;
    int bn = blockIdx.y * GBN;
    int t  = threadIdx.x;
    int wid = t >> 5;
    int wm  = wid >> 1;          // 0..3 : warp row (32 rows each)
    int wn  = wid & 1;           // 0..1 : warp col (32 cols each)

    // A loader: 128 rows x 64 halves; thread: row = t>>1, 32 halves at (t&1)*32
    int arow = t >> 1;
    int aseg = (t & 1) * 32;
    int gm_ld = bm + arow;
    // B loader: 64 rows(n) x 64 halves(k); thread: n = t>>2, 16 halves at (t&3)*16
    int brow = t >> 2;
    int bseg = (t & 3) * 16;

    wmma::fragment<wmma::accumulator, 16, 16, 16, float> c[2][2];
#pragma unroll
    for (int i = 0; i < 2; i++)
#pragma unroll
        for (int j = 0; j < 2; j++) wmma::fill_fragment(c[i][j], 0.0f);

    for (int k0 = 0; k0 < FDIM; k0 += GBK) {
        // load A tile (zero-fill OOB rows): 4x uint4 per thread
        uint4 a0 = make_uint4(0u,0u,0u,0u), a1 = a0, a2 = a0, a3 = a0;
        if (gm_ld < N_NODES) {
            const uint4* src = reinterpret_cast<const uint4*>(
                A + (size_t)gm_ld * FDIM + k0 + aseg);
            a0 = src[0]; a1 = src[1]; a2 = src[2]; a3 = src[3];
        }
        uint4* dstA = reinterpret_cast<uint4*>(&As[arow * LDA + aseg]);
        dstA[0] = a0; dstA[1] = a1; dstA[2] = a2; dstA[3] = a3;
        // load B tile (W rows bn..bn+63): 2x uint4 per thread
        const uint4* srcB = reinterpret_cast<const uint4*>(
            hW + (size_t)(bn + brow) * FDIM + k0 + bseg);
        uint4 b0 = srcB[0], b1 = srcB[1];
        uint4* dstB = reinterpret_cast<uint4*>(&Bs[brow * LDA + bseg]);
        dstB[0] = b0; dstB[1] = b1;
        __syncthreads();
#pragma unroll
        for (int kk = 0; kk < GBK; kk += 16) {
            wmma::fragment<wmma::matrix_a, 16, 16, 16, __half, wmma::row_major> af[2];
            wmma::fragment<wmma::matrix_b, 16, 16, 16, __half, wmma::col_major> bf[2];
#pragma unroll
            for (int i = 0; i < 2; i++)
                wmma::load_matrix_sync(af[i], &As[(wm * 32 + i * 16) * LDA + kk], LDA);
#pragma unroll
            for (int j = 0; j < 2; j++)
                wmma::load_matrix_sync(bf[j], &Bs[(wn * 32 + j * 16) * LDA + kk], LDA);
#pragma unroll
            for (int i = 0; i < 2; i++)
#pragma unroll
                for (int j = 0; j < 2; j++)
                    wmma::mma_sync(c[i][j], af[i], bf[j], c[i][j]);
        }
        __syncthreads();
    }

    // stage C to smem (overlaps As/Bs — separated by the final __syncthreads)
#pragma unroll
    for (int i = 0; i < 2; i++)
#pragma unroll
        for (int j = 0; j < 2; j++)
            wmma::store_matrix_sync(&Cs[(wm * 32 + i * 16) * LDC + wn * 32 + j * 16],
                                    c[i][j], LDC, wmma::mem_row_major);
    __syncthreads();

    // -------- epilogue: bias + PReLU + store + per-column partial stats ------
    int tn  = t & 15;          // 4-col group
    int tmg = t >> 4;          // 8-row group
    int n0 = bn + tn * 4;
    float4 bb  = *reinterpret_cast<const float4*>(&bias[n0]);
    float4 pwv = *reinterpret_cast<const float4*>(&pw[n0]);
    float cs[4]  = {0.f, 0.f, 0.f, 0.f};
    float cs2[4] = {0.f, 0.f, 0.f, 0.f};
#pragma unroll
    for (int r = 0; r < 8; r++) {
        int lr = tmg * 8 + r;
        int m  = bm + lr;
        float4 v = *reinterpret_cast<const float4*>(&Cs[lr * LDC + tn * 4]);
        v.x += bb.x; v.y += bb.y; v.z += bb.z; v.w += bb.w;
        v.x = (v.x >= 0.f) ? v.x : pwv.x * v.x;
        v.y = (v.y >= 0.f) ? v.y : pwv.y * v.y;
        v.z = (v.z >= 0.f) ? v.z : pwv.z * v.z;
        v.w = (v.w >= 0.f) ? v.w : pwv.w * v.w;
        if (m < N_NODES) {
            if (OUT_HALF) {
                __half2* dst = &g_hx0[m * FD2 + n0 / 2];
                dst[0] = __floats2half2_rn(v.x, v.y);
                dst[1] = __floats2half2_rn(v.z, v.w);
            } else {
                *reinterpret_cast<float4*>(&g_x0[(size_t)m * FDIM + n0]) = v;
            }
            cs[0] += v.x; cs[1] += v.y; cs[2] += v.z; cs[3] += v.w;
            cs2[0] += v.x * v.x; cs2[1] += v.y * v.y;
            cs2[2] += v.z * v.z; cs2[3] += v.w * v.w;
        }
    }

    // deterministic in-block column reduction (no atomics), single barrier
    int pbase = (blockIdx.y * GMB + blockIdx.x) * GBN;
#pragma unroll
    for (int i = 0; i < 4; i++) {
        Red1[tmg][tn * 4 + i] = cs[i];
        Red2[tmg][tn * 4 + i] = cs2[i];
    }
    __syncthreads();
    if (t < GBN) {
        float s = 0.f, s2 = 0.f;
#pragma unroll
        for (int r = 0; r < 16; r++) { s += Red1[r][t]; s2 += Red2[r][t]; }
        g_gp1[pbase + t] = s;
        g_gp2[pbase + t] = s2;
    }
}

// ------- BN finalize: 1024 threads, 4-way chunked, fixed combine order -----
__global__ void k_bn_finalize(const float* __restrict__ gamma,
                              const float* __restrict__ beta) {
    __shared__ float p1[4][FDIM];
    __shared__ float p2[4][FDIM];
    int f     = threadIdx.x & 255;
    int chunk = threadIdx.x >> 8;      // 0..3
    int by = f >> 6;
    int c  = f & 63;
    int bx0 = chunk * 59;
    int bx1 = (bx0 + 59 < GMB) ? bx0 + 59 : GMB;
    float s = 0.f, s2 = 0.f;
    for (int bx = bx0; bx < bx1; bx++) {
        int idx = (by * GMB + bx) * GBN + c;
        s  += g_gp1[idx];
        s2 += g_gp2[idx];
    }
    p1[chunk][f] = s;
    p2[chunk][f] = s2;
    __syncthreads();
    if (threadIdx.x < FDIM) {
        float S  = p1[0][f] + p1[1][f] + p1[2][f] + p1[3][f];   // fixed order
        float S2 = p2[0][f] + p2[1][f] + p2[2][f] + p2[3][f];
        float inv_n = 1.0f / (float)N_NODES;
        float mean = S * inv_n;
        float var  = S2 * inv_n - mean * mean;
        float sc   = gamma[f] * rsqrtf(var + BN_EPS);
        g_scale[f] = sc;
        g_shift[f] = beta[f] - mean * sc;
    }
}

// ---------------- final BN apply: g_x0 (fp32) -> d_out ----------------
__global__ void k_bn_apply_out(float* __restrict__ out_ext) {
    int i = blockIdx.x * blockDim.x + threadIdx.x;
    if (i >= NF4) return;
    int f4 = (i & 63) << 2;
    float4 v  = reinterpret_cast<const float4*>(g_x0)[i];
    float4 sc = *reinterpret_cast<const float4*>(&g_scale[f4]);
    float4 sh = *reinterpret_cast<const float4*>(&g_shift[f4]);
    v.x = v.x * sc.x + sh.x;
    v.y = v.y * sc.y + sh.y;
    v.z = v.z * sc.z + sh.z;
    v.w = v.w * sc.w + sh.w;
    reinterpret_cast<float4*>(out_ext)[i] = v;
}

// ---------------- launch ----------------
extern "C" void kernel_launch(void* const* d_in, const int* in_sizes, int n_in,
                              void* d_out, int out_size) {
    const float* cell  = (const float*)d_in[0];
    const float* sub   = (const float*)d_in[1];
    const int*   ei    = (const int*)  d_in[2];
    const float* ew    = (const float*)d_in[3];
    const float* W1    = (const float*)d_in[4];
    const float* b1    = (const float*)d_in[5];
    const float* W2    = (const float*)d_in[6];
    const float* b2    = (const float*)d_in[7];
    const float* pw    = (const float*)d_in[8];
    const float* gamma = (const float*)d_in[9];
    const float* beta  = (const float*)d_in[10];
    float* out = (float*)d_out;

    const int T = 256;
    // graph normalization setup (recomputed each call — deterministic work)
    k_concat_setup<<<(NF4 + T - 1) / T, T>>>((const float4*)cell,
                                             (const float4*)sub, W1, W2, ei, ew);
    k_scan_a<<<NBLK, 256>>>();             // decode+reset packed, local scan
    k_scan_c<<<NBLK, 256>>>();             // rescan totals + apply offsets
    k_scatter<<<(E_TOT / 8 + T - 1) / T, T>>>(ei, ew);

    dim3 ggrid(GMB, FDIM / GBN);   // (235, 4)
    const int SG = N_NODES / 8;    // 3750 blocks, 8 warps = 8 nodes each

    // ---- layer 1 (fp16 hops) ----
    k_spmm<true , false><<<SG, 256>>>();        // hx0 -> hx1
    k_spmm<false, false><<<SG, 256>>>();        // hx1 -> hx0
    k_spmm<true , false><<<SG, 256>>>();        // hx0 -> hx1
    k_gemm_tc<true , true ><<<ggrid, T>>>(b1, pw);  // hx1 -> hx0 (fp16) + stats
    k_bn_finalize<<<1, 1024>>>(gamma, beta);

    // ---- layer 2 (hop 1 folds layer-1 BN via linearity) ----
    k_spmm<true , true ><<<SG, 256>>>();        // hx0 -> hx1 (BN folded)
    k_spmm<false, false><<<SG, 256>>>();        // hx1 -> hx0
    k_spmm<true , false><<<SG, 256>>>();        // hx0 -> hx1
    k_gemm_tc<false, false><<<ggrid, T>>>(b2, pw);  // hx1 -> g_x0 (fp32) + stats
    k_bn_finalize<<<1, 1024>>>(gamma, beta);
    k_bn_apply_out<<<(NF4 + T - 1) / T, T>>>(out);  // g_x0 -> d_out (fp32)
}

// round 16
// speedup vs baseline: 1.4904x; 1.4904x over previous
#include <cuda_runtime.h>
#include <cuda_fp16.h>
#include <mma.h>

using namespace nvcuda;

// Problem constants (fixed shapes for this problem instance)
#define N_CELL   66
#define N_NODES  30000
#define FDIM     256
#define FD2      128               // half2 per row
#define E_TOT    960000            // directed edges (both directions)
#define NF       (N_NODES * FDIM)  // 7,680,000
#define NF4      (NF / 4)
#define CELL4    ((N_CELL * FDIM) / 4)
#define BN_EPS   1e-5f
#define FPSCALE  16777216.0f       // 2^24 fixed-point for packed degree
#define NBLK     118               // ceil(30000/256) scan blocks

// GEMM tiling
#define GBM 128
#define GBN 64
#define GBK 64
#define GMB 235                    // ceil(30000/128)
#define LDA 72                     // smem half stride (64 k + 8 pad)
#define LDC 72                     // smem float stride (64 n + 8 pad)

// ---------------- device scratch (static, no allocation) ----------------
// g_packed is zero at module load; k_scan_a re-zeros it after reading each
// call, so every kernel_launch (incl. graph replays) sees it zeroed.
__device__ __half2 g_hx0[N_NODES * FD2];   // fp16 feature ping
__device__ __half2 g_hx1[N_NODES * FD2];   // fp16 feature pong
__device__ float  g_x0[NF];                // fp32 GEMM2 output
__device__ __half g_hw1[FDIM * FDIM];      // fp16 W1
__device__ __half g_hw2[FDIM * FDIM];      // fp16 W2
__device__ unsigned long long g_packed[N_NODES];  // (count<<48)|fixed24.24 deg-1
__device__ float g_dinv[N_NODES];
__device__ int   g_colptr[N_NODES + 1];
__device__ int   g_cursor[N_NODES];
__device__ int   g_bsum[NBLK];
__device__ int2  g_epack[E_TOT];           // (src row, norm as bits)
__device__ float g_gp1[4 * GMB * GBN];     // per-block BN partial sums
__device__ float g_gp2[4 * GMB * GBN];     // per-block BN partial sumsq
__device__ float g_scale[FDIM];
__device__ float g_shift[FDIM];

// ------- setup: concat + fp16 quantize + W cvt + degree histogram ---------
// g_packed requires no init (zeroed at load / re-zeroed by k_scan_a).
__global__ void k_concat_setup(const float4* __restrict__ cell,
                               const float4* __restrict__ sub,
                               const float* __restrict__ W1,
                               const float* __restrict__ W2,
                               const int* __restrict__ ei,
                               const float* __restrict__ ew) {
    int i = blockIdx.x * blockDim.x + threadIdx.x;
    if (i < NF4) {
        float4 v = (i < CELL4) ? cell[i] : sub[i - CELL4];
        g_hx0[i * 2]     = __floats2half2_rn(v.x, v.y);
        g_hx0[i * 2 + 1] = __floats2half2_rn(v.z, v.w);
    }
    if (i < FDIM * FDIM) {
        g_hw1[i] = __float2half_rn(W1[i]);
        g_hw2[i] = __float2half_rn(W2[i]);
    }
    if (i < E_TOT) {
        int c = ei[E_TOT + i];             // target (col)
        unsigned long long add = (1ULL << 48) |
            (unsigned long long)__float2uint_rn(ew[i] * FPSCALE);
        atomicAdd(&g_packed[c], add);
    }
}

// ---- scan stage A: decode (+reset packed) + per-block exclusive scan ------
__global__ __launch_bounds__(256) void k_scan_a() {
    __shared__ int sm[256];
    int t = threadIdx.x;
    int i = blockIdx.x * 256 + t;
    int c = 0;
    if (i < N_NODES) {
        unsigned long long p = g_packed[i];
        g_packed[i] = 0ULL;                // leave zeroed for next call
        c = (int)(p >> 48);
        // self-loop weight 1.0 added here
        float deg = (float)(p & 0xFFFFFFFFFFFFULL) * (1.0f / FPSCALE) + 1.0f;
        g_dinv[i] = rsqrtf(deg);           // deg >= 1 always
    }
    sm[t] = c;
    __syncthreads();
#pragma unroll
    for (int off = 1; off < 256; off <<= 1) {
        int v = (t >= off) ? sm[t - off] : 0;
        __syncthreads();
        sm[t] += v;
        __syncthreads();
    }
    if (i < N_NODES) g_colptr[i] = sm[t] - c;        // local exclusive prefix
    if (t == 255) g_bsum[blockIdx.x] = sm[255];      // block total
}

// ---- scan stage C: every block rescans the 118 block totals (redundant) ---
__global__ __launch_bounds__(256) void k_scan_c() {
    __shared__ int sm[128];
    int t = threadIdx.x;
    if (t < 128) {
        int v = (t < NBLK) ? g_bsum[t] : 0;
        sm[t] = v;
    }
    __syncthreads();
#pragma unroll
    for (int off = 1; off < 128; off <<= 1) {
        int u = 0;
        if (t < 128 && t >= off) u = sm[t - off];
        __syncthreads();
        if (t < 128) sm[t] += u;
        __syncthreads();
    }
    int boff = (blockIdx.x == 0) ? 0 : sm[blockIdx.x - 1];
    int i = blockIdx.x * 256 + t;
    if (i < N_NODES) {
        int v = g_colptr[i] + boff;
        g_colptr[i] = v;
        g_cursor[i] = v;
    }
    if (blockIdx.x == 0 && t == 0) g_colptr[N_NODES] = E_TOT;
}

// 4 edges per thread for MLP over the ATOMG latency
__global__ void k_scatter(const int* __restrict__ ei, const float* __restrict__ ew) {
    int e = (blockIdx.x * blockDim.x + threadIdx.x) * 4;
    if (e >= E_TOT) return;
    int4   r4 = *reinterpret_cast<const int4*>(&ei[e]);
    int4   c4 = *reinterpret_cast<const int4*>(&ei[E_TOT + e]);
    float4 w4 = *reinterpret_cast<const float4*>(&ew[e]);
    float n0 = g_dinv[r4.x] * w4.x * g_dinv[c4.x];
    float n1 = g_dinv[r4.y] * w4.y * g_dinv[c4.y];
    float n2 = g_dinv[r4.z] * w4.z * g_dinv[c4.z];
    float n3 = g_dinv[r4.w] * w4.w * g_dinv[c4.w];
    int p0 = atomicAdd(&g_cursor[c4.x], 1);
    int p1 = atomicAdd(&g_cursor[c4.y], 1);
    int p2 = atomicAdd(&g_cursor[c4.z], 1);
    int p3 = atomicAdd(&g_cursor[c4.w], 1);
    g_epack[p0] = make_int2(r4.x, __float_as_int(n0));
    g_epack[p1] = make_int2(r4.y, __float_as_int(n1));
    g_epack[p2] = make_int2(r4.z, __float_as_int(n2));
    g_epack[p3] = make_int2(r4.w, __float_as_int(n3));
}

// ---------------- SpMM: one WARP per destination node, zero sync ----------
// Lane owns 8 features (16B, LDG.128). Warp walks its node's full edge list.
// SRC0: src = hx0, dst = hx1 (else swapped)
// FOLD: out = scale[f]*acc + shift[f]*sum_w   (BN applied via linearity)
template <bool SRC0, bool FOLD>
__global__ __launch_bounds__(256) void k_spmm() {
    const __half2* __restrict__ xin  = SRC0 ? g_hx0 : g_hx1;
    __half2*       __restrict__ xout = SRC0 ? g_hx1 : g_hx0;

    int node = blockIdx.x * 8 + (threadIdx.x >> 5);   // grid 3750 * 8 = 30000
    int lid  = threadIdx.x & 31;
    int beg = g_colptr[node];
    int end = g_colptr[node + 1];
    float di = g_dinv[node];
    float selfw = di * di;

    // self-loop term
    uint4 s = *reinterpret_cast<const uint4*>(&xin[node * FD2 + lid * 4]);
    float2 s0 = __half22float2(*reinterpret_cast<__half2*>(&s.x));
    float2 s1 = __half22float2(*reinterpret_cast<__half2*>(&s.y));
    float2 s2 = __half22float2(*reinterpret_cast<__half2*>(&s.z));
    float2 s3 = __half22float2(*reinterpret_cast<__half2*>(&s.w));
    float acc[8];
    acc[0] = selfw * s0.x; acc[1] = selfw * s0.y;
    acc[2] = selfw * s1.x; acc[3] = selfw * s1.y;
    acc[4] = selfw * s2.x; acc[5] = selfw * s2.y;
    acc[6] = selfw * s3.x; acc[7] = selfw * s3.y;
    float sw = selfw;   // only used when FOLD

#pragma unroll 8
    for (int e = beg; e < end; e++) {
        int2 p = g_epack[e];                 // warp-uniform, L1-resident
        float w = __int_as_float(p.y);
        uint4 d = *reinterpret_cast<const uint4*>(&xin[p.x * FD2 + lid * 4]);
        float2 f0 = __half22float2(*reinterpret_cast<__half2*>(&d.x));
        float2 f1 = __half22float2(*reinterpret_cast<__half2*>(&d.y));
        float2 f2 = __half22float2(*reinterpret_cast<__half2*>(&d.z));
        float2 f3 = __half22float2(*reinterpret_cast<__half2*>(&d.w));
        acc[0] += w * f0.x; acc[1] += w * f0.y;
        acc[2] += w * f1.x; acc[3] += w * f1.y;
        acc[4] += w * f2.x; acc[5] += w * f2.y;
        acc[6] += w * f3.x; acc[7] += w * f3.y;
        if (FOLD) sw += w;                   // lane-uniform, no reduction needed
    }

    if (FOLD) {
        int f0 = lid * 8;
        float4 sca = *reinterpret_cast<const float4*>(&g_scale[f0]);
        float4 scb = *reinterpret_cast<const float4*>(&g_scale[f0 + 4]);
        float4 sha = *reinterpret_cast<const float4*>(&g_shift[f0]);
        float4 shb = *reinterpret_cast<const float4*>(&g_shift[f0 + 4]);
        acc[0] = sca.x * acc[0] + sha.x * sw;
        acc[1] = sca.y * acc[1] + sha.y * sw;
        acc[2] = sca.z * acc[2] + sha.z * sw;
        acc[3] = sca.w * acc[3] + sha.w * sw;
        acc[4] = scb.x * acc[4] + shb.x * sw;
        acc[5] = scb.y * acc[5] + shb.y * sw;
        acc[6] = scb.z * acc[6] + shb.z * sw;
        acc[7] = scb.w * acc[7] + shb.w * sw;
    }

    uint4 o;
    *reinterpret_cast<__half2*>(&o.x) = __floats2half2_rn(acc[0], acc[1]);
    *reinterpret_cast<__half2*>(&o.y) = __floats2half2_rn(acc[2], acc[3]);
    *reinterpret_cast<__half2*>(&o.z) = __floats2half2_rn(acc[4], acc[5]);
    *reinterpret_cast<__half2*>(&o.w) = __floats2half2_rn(acc[6], acc[7]);
    *reinterpret_cast<uint4*>(&xout[node * FD2 + lid * 4]) = o;
}

// ------- fused tensor-core GEMM: C = prelu(A @ W^T + b), + BN stats --------
// A = g_hx1 [N,256] fp16 row-major.  W fp16 [256,256] row-major (= B col-major).
// USE_W1 selects the __device__ weight array; OUT_HALF -> g_hx0 else g_x0.
template <bool USE_W1, bool OUT_HALF>
__global__ __launch_bounds__(256) void k_gemm_tc(const float* __restrict__ bias,
                                                 const float* __restrict__ pw) {
    // smem: mainloop A/B tiles overlap epilogue C staging; dual reduction bufs
    __shared__ __align__(16) unsigned char raw[GBM * LDC * 4 + 32 * GBN * 4];
    __half* As = reinterpret_cast<__half*>(raw);                 // [128][LDA]
    __half* Bs = reinterpret_cast<__half*>(raw + GBM * LDA * 2); // [64][LDA]
    float*  Cs = reinterpret_cast<float*>(raw);                  // [128][LDC]
    float(*Red1)[GBN] = reinterpret_cast<float(*)[GBN]>(raw + GBM * LDC * 4);
    float(*Red2)[GBN] = reinterpret_cast<float(*)[GBN]>(raw + GBM * LDC * 4 + 16 * GBN * 4);

    const __half* __restrict__ A  = reinterpret_cast<const __half*>(g_hx1);
    const __half* __restrict__ hW = USE_W1 ? g_hw1 : g_hw2;

    int bm = blockIdx.x * GBM;
    int bn = blockIdx.y * GBN;
    int t  = threadIdx.x;
    int wid = t >> 5;
    int wm  = wid >> 1;          // 0..3 : warp row (32 rows each)
    int wn  = wid & 1;           // 0..1 : warp col (32 cols each)

    // A loader: 128 rows x 64 halves; thread: row = t>>1, 32 halves at (t&1)*32
    int arow = t >> 1;
    int aseg = (t & 1) * 32;
    int gm_ld = bm + arow;
    // B loader: 64 rows(n) x 64 halves(k); thread: n = t>>2, 16 halves at (t&3)*16
    int brow = t >> 2;
    int bseg = (t & 3) * 16;

    wmma::fragment<wmma::accumulator, 16, 16, 16, float> c[2][2];
#pragma unroll
    for (int i = 0; i < 2; i++)
#pragma unroll
        for (int j = 0; j < 2; j++) wmma::fill_fragment(c[i][j], 0.0f);

    for (int k0 = 0; k0 < FDIM; k0 += GBK) {
        // load A tile (zero-fill OOB rows): 4x uint4 per thread
        uint4 a0 = make_uint4(0u,0u,0u,0u), a1 = a0, a2 = a0, a3 = a0;
        if (gm_ld < N_NODES) {
            const uint4* src = reinterpret_cast<const uint4*>(
                A + (size_t)gm_ld * FDIM + k0 + aseg);
            a0 = src[0]; a1 = src[1]; a2 = src[2]; a3 = src[3];
        }
        uint4* dstA = reinterpret_cast<uint4*>(&As[arow * LDA + aseg]);
        dstA[0] = a0; dstA[1] = a1; dstA[2] = a2; dstA[3] = a3;
        // load B tile (W rows bn..bn+63): 2x uint4 per thread
        const uint4* srcB = reinterpret_cast<const uint4*>(
            hW + (size_t)(bn + brow) * FDIM + k0 + bseg);
        uint4 b0 = srcB[0], b1 = srcB[1];
        uint4* dstB = reinterpret_cast<uint4*>(&Bs[brow * LDA + bseg]);
        dstB[0] = b0; dstB[1] = b1;
        __syncthreads();
#pragma unroll
        for (int kk = 0; kk < GBK; kk += 16) {
            wmma::fragment<wmma::matrix_a, 16, 16, 16, __half, wmma::row_major> af[2];
            wmma::fragment<wmma::matrix_b, 16, 16, 16, __half, wmma::col_major> bf[2];
#pragma unroll
            for (int i = 0; i < 2; i++)
                wmma::load_matrix_sync(af[i], &As[(wm * 32 + i * 16) * LDA + kk], LDA);
#pragma unroll
            for (int j = 0; j < 2; j++)
                wmma::load_matrix_sync(bf[j], &Bs[(wn * 32 + j * 16) * LDA + kk], LDA);
#pragma unroll
            for (int i = 0; i < 2; i++)
#pragma unroll
                for (int j = 0; j < 2; j++)
                    wmma::mma_sync(c[i][j], af[i], bf[j], c[i][j]);
        }
        __syncthreads();
    }

    // stage C to smem (overlaps As/Bs — separated by the final __syncthreads)
#pragma unroll
    for (int i = 0; i < 2; i++)
#pragma unroll
        for (int j = 0; j < 2; j++)
            wmma::store_matrix_sync(&Cs[(wm * 32 + i * 16) * LDC + wn * 32 + j * 16],
                                    c[i][j], LDC, wmma::mem_row_major);
    __syncthreads();

    // -------- epilogue: bias + PReLU + store + per-column partial stats ------
    int tn  = t & 15;          // 4-col group
    int tmg = t >> 4;          // 8-row group
    int n0 = bn + tn * 4;
    float4 bb  = *reinterpret_cast<const float4*>(&bias[n0]);
    float4 pwv = *reinterpret_cast<const float4*>(&pw[n0]);
    float cs[4]  = {0.f, 0.f, 0.f, 0.f};
    float cs2[4] = {0.f, 0.f, 0.f, 0.f};
#pragma unroll
    for (int r = 0; r < 8; r++) {
        int lr = tmg * 8 + r;
        int m  = bm + lr;
        float4 v = *reinterpret_cast<const float4*>(&Cs[lr * LDC + tn * 4]);
        v.x += bb.x; v.y += bb.y; v.z += bb.z; v.w += bb.w;
        v.x = (v.x >= 0.f) ? v.x : pwv.x * v.x;
        v.y = (v.y >= 0.f) ? v.y : pwv.y * v.y;
        v.z = (v.z >= 0.f) ? v.z : pwv.z * v.z;
        v.w = (v.w >= 0.f) ? v.w : pwv.w * v.w;
        if (m < N_NODES) {
            if (OUT_HALF) {
                __half2* dst = &g_hx0[m * FD2 + n0 / 2];
                dst[0] = __floats2half2_rn(v.x, v.y);
                dst[1] = __floats2half2_rn(v.z, v.w);
            } else {
                *reinterpret_cast<float4*>(&g_x0[(size_t)m * FDIM + n0]) = v;
            }
            cs[0] += v.x; cs[1] += v.y; cs[2] += v.z; cs[3] += v.w;
            cs2[0] += v.x * v.x; cs2[1] += v.y * v.y;
            cs2[2] += v.z * v.z; cs2[3] += v.w * v.w;
        }
    }

    // deterministic in-block column reduction (no atomics), single barrier
    int pbase = (blockIdx.y * GMB + blockIdx.x) * GBN;
#pragma unroll
    for (int i = 0; i < 4; i++) {
        Red1[tmg][tn * 4 + i] = cs[i];
        Red2[tmg][tn * 4 + i] = cs2[i];
    }
    __syncthreads();
    if (t < GBN) {
        float s = 0.f, s2 = 0.f;
#pragma unroll
        for (int r = 0; r < 16; r++) { s += Red1[r][t]; s2 += Red2[r][t]; }
        g_gp1[pbase + t] = s;
        g_gp2[pbase + t] = s2;
    }
}

// ------- BN finalize: 1024 threads, 4-way chunked, fixed combine order -----
__global__ void k_bn_finalize(const float* __restrict__ gamma,
                              const float* __restrict__ beta) {
    __shared__ float p1[4][FDIM];
    __shared__ float p2[4][FDIM];
    int f     = threadIdx.x & 255;
    int chunk = threadIdx.x >> 8;      // 0..3
    int by = f >> 6;
    int c  = f & 63;
    int bx0 = chunk * 59;
    int bx1 = (bx0 + 59 < GMB) ? bx0 + 59 : GMB;
    float s = 0.f, s2 = 0.f;
    for (int bx = bx0; bx < bx1; bx++) {
        int idx = (by * GMB + bx) * GBN + c;
        s  += g_gp1[idx];
        s2 += g_gp2[idx];
    }
    p1[chunk][f] = s;
    p2[chunk][f] = s2;
    __syncthreads();
    if (threadIdx.x < FDIM) {
        float S  = p1[0][f] + p1[1][f] + p1[2][f] + p1[3][f];   // fixed order
        float S2 = p2[0][f] + p2[1][f] + p2[2][f] + p2[3][f];
        float inv_n = 1.0f / (float)N_NODES;
        float mean = S * inv_n;
        float var  = S2 * inv_n - mean * mean;
        float sc   = gamma[f] * rsqrtf(var + BN_EPS);
        g_scale[f] = sc;
        g_shift[f] = beta[f] - mean * sc;
    }
}

// ---------------- final BN apply: g_x0 (fp32) -> d_out ----------------
__global__ void k_bn_apply_out(float* __restrict__ out_ext) {
    int i = blockIdx.x * blockDim.x + threadIdx.x;
    if (i >= NF4) return;
    int f4 = (i & 63) << 2;
    float4 v  = reinterpret_cast<const float4*>(g_x0)[i];
    float4 sc = *reinterpret_cast<const float4*>(&g_scale[f4]);
    float4 sh = *reinterpret_cast<const float4*>(&g_shift[f4]);
    v.x = v.x * sc.x + sh.x;
    v.y = v.y * sc.y + sh.y;
    v.z = v.z * sc.z + sh.z;
    v.w = v.w * sc.w + sh.w;
    reinterpret_cast<float4*>(out_ext)[i] = v;
}

// ---------------- launch ----------------
extern "C" void kernel_launch(void* const* d_in, const int* in_sizes, int n_in,
                              void* d_out, int out_size) {
    const float* cell  = (const float*)d_in[0];
    const float* sub   = (const float*)d_in[1];
    const int*   ei    = (const int*)  d_in[2];
    const float* ew    = (const float*)d_in[3];
    const float* W1    = (const float*)d_in[4];
    const float* b1    = (const float*)d_in[5];
    const float* W2    = (const float*)d_in[6];
    const float* b2    = (const float*)d_in[7];
    const float* pw    = (const float*)d_in[8];
    const float* gamma = (const float*)d_in[9];
    const float* beta  = (const float*)d_in[10];
    float* out = (float*)d_out;

    const int T = 256;
    // graph normalization setup (recomputed each call — deterministic work)
    k_concat_setup<<<(NF4 + T - 1) / T, T>>>((const float4*)cell,
                                             (const float4*)sub, W1, W2, ei, ew);
    k_scan_a<<<NBLK, 256>>>();             // decode+reset packed, local scan
    k_scan_c<<<NBLK, 256>>>();             // rescan totals + apply offsets
    k_scatter<<<(E_TOT / 4 + T - 1) / T, T>>>(ei, ew);

    dim3 ggrid(GMB, FDIM / GBN);   // (235, 4)
    const int SG = N_NODES / 8;    // 3750 blocks, 8 warps = 8 nodes each

    // ---- layer 1 (fp16 hops) ----
    k_spmm<true , false><<<SG, 256>>>();        // hx0 -> hx1
    k_spmm<false, false><<<SG, 256>>>();        // hx1 -> hx0
    k_spmm<true , false><<<SG, 256>>>();        // hx0 -> hx1
    k_gemm_tc<true , true ><<<ggrid, T>>>(b1, pw);  // hx1 -> hx0 (fp16) + stats
    k_bn_finalize<<<1, 1024>>>(gamma, beta);

    // ---- layer 2 (hop 1 folds layer-1 BN via linearity) ----
    k_spmm<true , true ><<<SG, 256>>>();        // hx0 -> hx1 (BN folded)
    k_spmm<false, false><<<SG, 256>>>();        // hx1 -> hx0
    k_spmm<true , false><<<SG, 256>>>();        // hx0 -> hx1
    k_gemm_tc<false, false><<<ggrid, T>>>(b2, pw);  // hx1 -> g_x0 (fp32) + stats
    k_bn_finalize<<<1, 1024>>>(gamma, beta);
    k_bn_apply_out<<<(NF4 + T - 1) / T, T>>>(out);  // g_x0 -> d_out (fp32)
}